// round 4
// baseline (speedup 1.0000x reference)
#include <cuda_runtime.h>
#include <cuda_bf16.h>

typedef unsigned long long ULL;

// ---------------- f32x2 packed helpers (sm_100+) ----------------
__device__ __forceinline__ ULL ffma2(ULL a, ULL b, ULL c) {
    ULL d;
    asm("fma.rn.f32x2 %0, %1, %2, %3;" : "=l"(d) : "l"(a), "l"(b), "l"(c));
    return d;
}
__device__ __forceinline__ ULL fadd2(ULL a, ULL b) {
    ULL d;
    asm("add.rn.f32x2 %0, %1, %2;" : "=l"(d) : "l"(a), "l"(b));
    return d;
}
__device__ __forceinline__ ULL dup2(float w) {
    unsigned u = __float_as_uint(w);
    ULL d;
    asm("mov.b64 %0, {%1, %1};" : "=l"(d) : "r"(u));
    return d;
}
__device__ __forceinline__ ULL pack2(float lo, float hi) {
    ULL d;
    unsigned a = __float_as_uint(lo), b = __float_as_uint(hi);
    asm("mov.b64 %0, {%1, %2};" : "=l"(d) : "r"(a), "r"(b));
    return d;
}
__device__ __forceinline__ void unpack2(ULL v, float& lo, float& hi) {
    unsigned a, b;
    asm("mov.b64 {%0, %1}, %2;" : "=r"(a), "=r"(b) : "l"(v));
    lo = __uint_as_float(a);
    hi = __uint_as_float(b);
}

// tanh(x) = 1 - 2/(exp(2x)+1), via MUFU.EX2 + MUFU.RCP.
// Saturates exactly to +/-1 for large |x| (inf/0 paths are clean).
__device__ __forceinline__ float fast_tanh(float x) {
    float t = x * 2.885390081777927f;  // 2*log2(e)
    float e;
    asm("ex2.approx.f32 %0, %1;" : "=f"(e) : "f"(t));
    float r;
    asm("rcp.approx.f32 %0, %1;" : "=f"(r) : "f"(e + 1.0f));
    return fmaf(-2.0f, r, 1.0f);
}

// ---------------- config ----------------
// B=4096, T=2048, F=8, H=32, O=8
// 1 warp handles 2 batch rows (f32x2 pair; lane l owns h-element l of both).
// 1024 blocks x 64 threads = 2048 warps = 4096 rows.
// Load balance: 2048 warps / 148 SMs -> max 14 warps/SM with 2-warp blocks
// (a 4-warp/512-block config quantizes to 16 warps on the slowest SMs).
#define TT    2048
#define FF    8
#define HH    32
#define OO    8
#define CHUNK 8                 // timesteps of x staged per SMEM refill
#define WPB   2                 // warps per block

__global__ void __launch_bounds__(64, 7)
rnn_fused_kernel(const float* __restrict__ x,
                 const float* __restrict__ W_ih,
                 const float* __restrict__ W_hh,
                 const float* __restrict__ b_ih,
                 const float* __restrict__ b_hh,
                 const float* __restrict__ W_out,
                 const float* __restrict__ b_out,
                 float* __restrict__ out)
{
    // Per-warp double-buffered h (interleaved pairs) and x chunk staging.
    __shared__ __align__(16) ULL hbuf[WPB][2][HH];          // 1 KB
    __shared__ __align__(16) ULL xbuf[WPB][2][CHUNK * FF];  // 2 KB

    const int tid  = threadIdx.x;
    const int wip  = tid >> 5;
    const int lane = tid & 31;
    const int w    = blockIdx.x * WPB + wip;    // 0..2047
    const size_t b0 = (size_t)2 * w;
    const size_t b1 = b0 + 1;

    // ---- weights into registers, duplicated for f32x2 ----
    ULL w2[HH];          // W_hh row `lane`, each element as (w,w)
    {
        const float4* wr = (const float4*)(W_hh + lane * HH);
        #pragma unroll
        for (int k = 0; k < HH / 4; ++k) {
            float4 v = wr[k];
            w2[4 * k + 0] = dup2(v.x);
            w2[4 * k + 1] = dup2(v.y);
            w2[4 * k + 2] = dup2(v.z);
            w2[4 * k + 3] = dup2(v.w);
        }
    }
    ULL wih2[FF];        // W_ih row `lane`
    {
        const float4* wr = (const float4*)(W_ih + lane * FF);
        #pragma unroll
        for (int k = 0; k < FF / 4; ++k) {
            float4 v = wr[k];
            wih2[4 * k + 0] = dup2(v.x);
            wih2[4 * k + 1] = dup2(v.y);
            wih2[4 * k + 2] = dup2(v.z);
            wih2[4 * k + 3] = dup2(v.w);
        }
    }
    const ULL bias2 = dup2(b_ih[lane] + b_hh[lane]);

    hbuf[wip][0][lane] = 0ULL;   // h0 = 0 (both rows)

    const float* xa = x + b0 * (size_t)(TT * FF);
    const float* xb = x + b1 * (size_t)(TT * FF);

    // prefetch chunk 0: lanes 0-15 cover row b0's 64 floats, 16-31 cover b1's
    float4 pre;
    {
        const float4* p = (lane < 16) ? (const float4*)xa + lane
                                      : (const float4*)xb + (lane - 16);
        pre = *p;
    }

    const int NCHUNK = TT / CHUNK;   // 256
    for (int c = 0; c < NCHUNK; ++c) {
        // stage prefetched chunk, interleaved (xa, xb) pairs
        {
            float* xs = (float*)&xbuf[wip][c & 1][0];
            const int base = (lane < 16) ? 4 * lane : 4 * (lane - 16);
            const int off  = (lane < 16) ? 0 : 1;
            xs[(base + 0) * 2 + off] = pre.x;
            xs[(base + 1) * 2 + off] = pre.y;
            xs[(base + 2) * 2 + off] = pre.z;
            xs[(base + 3) * 2 + off] = pre.w;
        }
        if (c + 1 < NCHUNK) {
            const float4* p = (lane < 16)
                ? (const float4*)(xa + (size_t)(c + 1) * CHUNK * FF) + lane
                : (const float4*)(xb + (size_t)(c + 1) * CHUNK * FF) + (lane - 16);
            pre = *p;
        }
        __syncwarp();

        const ULL* xs = &xbuf[wip][c & 1][0];
        #pragma unroll
        for (int s = 0; s < CHUNK; ++s) {
            const int t = c * CHUNK + s;
            const ULL* hr = &hbuf[wip][t & 1][0];

            // two accumulator chains to shorten dependent-FMA latency
            ULL acc0 = bias2;
            ULL acc1 = 0ULL;

            // input projection: xp = W_ih @ x_t (+bias already in acc0)
            #pragma unroll
            for (int f = 0; f < FF; f += 2) {
                ulonglong2 xv = *(const ulonglong2*)&xs[s * FF + f];
                acc0 = ffma2(xv.x, wih2[f], acc0);
                acc1 = ffma2(xv.y, wih2[f + 1], acc1);
            }
            // recurrent matvec: + W_hh[lane,:] . h
            #pragma unroll
            for (int j = 0; j < HH; j += 2) {
                ulonglong2 hv = *(const ulonglong2*)&hr[j];
                acc0 = ffma2(hv.x, w2[j], acc0);
                acc1 = ffma2(hv.y, w2[j + 1], acc1);
            }
            ULL acc = fadd2(acc0, acc1);

            float lo, hi;
            unpack2(acc, lo, hi);
            lo = fast_tanh(lo);
            hi = fast_tanh(hi);

            hbuf[wip][(t + 1) & 1][lane] = pack2(lo, hi);
            __syncwarp();
        }
    }

    // ---- output head: y = h_final @ W_out^T + b_out ----
    // T=2048 even -> final h sits in buffer 0; last __syncwarp already done.
    if (lane < OO) {
        const ULL* hf = &hbuf[wip][0][0];
        float ya = b_out[lane];
        float yb = ya;
        #pragma unroll
        for (int j = 0; j < HH; ++j) {
            float ha, hb;
            unpack2(hf[j], ha, hb);
            const float wv = W_out[lane * HH + j];
            ya = fmaf(wv, ha, ya);
            yb = fmaf(wv, hb, yb);
        }
        out[b0 * OO + lane] = ya;
        out[b1 * OO + lane] = yb;
    }
}

extern "C" void kernel_launch(void* const* d_in, const int* in_sizes, int n_in,
                              void* d_out, int out_size)
{
    const float* x     = (const float*)d_in[0];
    const float* W_ih  = (const float*)d_in[1];
    const float* W_hh  = (const float*)d_in[2];
    const float* b_ih  = (const float*)d_in[3];
    const float* b_hh  = (const float*)d_in[4];
    const float* W_out = (const float*)d_in[5];
    const float* b_out = (const float*)d_in[6];
    float* out = (float*)d_out;

    // 4096 rows / 2 per warp / 2 warps per block = 1024 blocks (one wave,
    // max 14 warps per SM)
    rnn_fused_kernel<<<1024, 64>>>(x, W_ih, W_hh, b_ih, b_hh, W_out, b_out, out);
}

// round 5
// speedup vs baseline: 1.0897x; 1.0897x over previous
#include <cuda_runtime.h>
#include <cuda_bf16.h>

typedef unsigned long long ULL;

// ---------------- f32x2 packed helpers (sm_100+) ----------------
__device__ __forceinline__ ULL ffma2(ULL a, ULL b, ULL c) {
    ULL d;
    asm("fma.rn.f32x2 %0, %1, %2, %3;" : "=l"(d) : "l"(a), "l"(b), "l"(c));
    return d;
}
__device__ __forceinline__ ULL fadd2(ULL a, ULL b) {
    ULL d;
    asm("add.rn.f32x2 %0, %1, %2;" : "=l"(d) : "l"(a), "l"(b));
    return d;
}
__device__ __forceinline__ ULL dup2(float w) {
    unsigned u = __float_as_uint(w);
    ULL d;
    asm("mov.b64 %0, {%1, %1};" : "=l"(d) : "r"(u));
    return d;
}
__device__ __forceinline__ ULL pack2(float lo, float hi) {
    ULL d;
    unsigned a = __float_as_uint(lo), b = __float_as_uint(hi);
    asm("mov.b64 %0, {%1, %2};" : "=l"(d) : "r"(a), "r"(b));
    return d;
}
__device__ __forceinline__ void unpack2(ULL v, float& lo, float& hi) {
    unsigned a, b;
    asm("mov.b64 {%0, %1}, %2;" : "=r"(a), "=r"(b) : "l"(v));
    lo = __uint_as_float(a);
    hi = __uint_as_float(b);
}

// Weights are pre-scaled by C = 2*log2(e), so the accumulator directly holds
// u = 2*log2(e)*a. tanh(a) = 1 - 2/(exp(2a)+1) = 1 - 2/(exp2(u)+1).
// Saturates exactly to +/-1 for large |a|.
__device__ __forceinline__ float tanh_from_scaled(float u) {
    float e;
    asm("ex2.approx.f32 %0, %1;" : "=f"(e) : "f"(u));
    float r;
    asm("rcp.approx.f32 %0, %1;" : "=f"(r) : "f"(e + 1.0f));
    return fmaf(-2.0f, r, 1.0f);
}

// ---------------- config ----------------
// B=4096, T=2048, F=8, H=32, O=8
// One 32-thread block = one warp = 4 batch rows (2 f32x2 pairs).
// Lanes 0-15 own pair 0, lanes 16-31 own pair 1. Each lane computes output
// rows llo and llo+16 of its pair (W_hh rows llo, llo+16 in registers).
// => one LDS.128 of h serves BOTH pairs (two 16-lane broadcast groups),
// halving shared-memory traffic per batch row vs the 2-row/warp version
// (R4 ncu: L1 pipe 83.9% = bottleneck).
#define TT    2048
#define FF    8
#define HH    32
#define OO    8
#define CHUNK 8       // timesteps of x staged per SMEM refill
#define HPAD  34      // ULL stride between pair h buffers (272B: +4 banks, no
                      // cross-half-warp bank conflict on simultaneous loads)
#define XPAD  66      // ULL stride between pair x buffers (528B: +4 banks)

__global__ void __launch_bounds__(32, 7)
rnn_fused_kernel(const float* __restrict__ x,
                 const float* __restrict__ W_ih,
                 const float* __restrict__ W_hh,
                 const float* __restrict__ b_ih,
                 const float* __restrict__ b_hh,
                 const float* __restrict__ W_out,
                 const float* __restrict__ b_out,
                 float* __restrict__ out)
{
    // Double-buffered h and x-chunk staging, per pair, interleaved (rowA,rowB).
    __shared__ __align__(16) ULL hb[2][2][HPAD];  // [buf][pair][32 + pad]
    __shared__ __align__(16) ULL xb[2][2][XPAD];  // [buf][pair][64 + pad]

    const int lane = threadIdx.x;       // 0..31
    const int llo  = lane & 15;
    const int half = lane >> 4;         // which pair this lane processes
    const size_t base = (size_t)blockIdx.x * 4;  // first of 4 batch rows

    const float C = 2.885390081777927f; // 2*log2(e), folded into weights

    // ---- weights into registers: W_hh rows llo and llo+16, scaled, dup'd ----
    ULL wA[HH], wB[HH];
    {
        const float4* ra = (const float4*)(W_hh + llo * HH);
        const float4* rb = (const float4*)(W_hh + (llo + 16) * HH);
        #pragma unroll
        for (int k = 0; k < HH / 4; ++k) {
            float4 va = ra[k], vb = rb[k];
            wA[4*k+0] = dup2(C*va.x); wA[4*k+1] = dup2(C*va.y);
            wA[4*k+2] = dup2(C*va.z); wA[4*k+3] = dup2(C*va.w);
            wB[4*k+0] = dup2(C*vb.x); wB[4*k+1] = dup2(C*vb.y);
            wB[4*k+2] = dup2(C*vb.z); wB[4*k+3] = dup2(C*vb.w);
        }
    }
    ULL wihA[FF], wihB[FF];
    {
        const float4* ra = (const float4*)(W_ih + llo * FF);
        const float4* rb = (const float4*)(W_ih + (llo + 16) * FF);
        #pragma unroll
        for (int k = 0; k < FF / 4; ++k) {
            float4 va = ra[k], vb = rb[k];
            wihA[4*k+0] = dup2(C*va.x); wihA[4*k+1] = dup2(C*va.y);
            wihA[4*k+2] = dup2(C*va.z); wihA[4*k+3] = dup2(C*va.w);
            wihB[4*k+0] = dup2(C*vb.x); wihB[4*k+1] = dup2(C*vb.y);
            wihB[4*k+2] = dup2(C*vb.z); wihB[4*k+3] = dup2(C*vb.w);
        }
    }
    const ULL biasA = dup2(C * (b_ih[llo]      + b_hh[llo]));
    const ULL biasB = dup2(C * (b_ih[llo + 16] + b_hh[llo + 16]));

    // h0 = 0 for both pairs
    hb[0][half][llo]      = 0ULL;
    hb[0][half][llo + 16] = 0ULL;

    // ---- x chunk prefetch: 4 rows x 64 floats = 64 float4, 2 per lane ----
    // global float4 index i: row = i>>4 (0..3), pos = i&15
    float4 pre0, pre1;
    {
        const int i0 = lane, i1 = lane + 32;
        const float* p0 = x + (base + (i0 >> 4)) * (size_t)(TT * FF) + (i0 & 15) * 4;
        const float* p1 = x + (base + (i1 >> 4)) * (size_t)(TT * FF) + (i1 & 15) * 4;
        pre0 = *(const float4*)p0;
        pre1 = *(const float4*)p1;
    }

    const int NCHUNK = TT / CHUNK;   // 256
    for (int c = 0; c < NCHUNK; ++c) {
        // stage prefetched chunk: interleaved (rowEven, rowOdd) per pair
        {
            const int buf = c & 1;
            #pragma unroll
            for (int k = 0; k < 2; ++k) {
                const int i    = lane + 32 * k;
                const int row  = i >> 4;
                const int pos  = i & 15;
                const int pair = row >> 1;
                const int slot = row & 1;
                float*  xs = (float*)&xb[buf][pair][0];
                const float4 v = (k == 0) ? pre0 : pre1;
                xs[(pos*4 + 0) * 2 + slot] = v.x;
                xs[(pos*4 + 1) * 2 + slot] = v.y;
                xs[(pos*4 + 2) * 2 + slot] = v.z;
                xs[(pos*4 + 3) * 2 + slot] = v.w;
            }
        }
        if (c + 1 < NCHUNK) {
            const int i0 = lane, i1 = lane + 32;
            const float* p0 = x + (base + (i0 >> 4)) * (size_t)(TT * FF)
                                + (size_t)(c + 1) * (CHUNK * FF) + (i0 & 15) * 4;
            const float* p1 = x + (base + (i1 >> 4)) * (size_t)(TT * FF)
                                + (size_t)(c + 1) * (CHUNK * FF) + (i1 & 15) * 4;
            pre0 = *(const float4*)p0;
            pre1 = *(const float4*)p1;
        }
        __syncwarp();

        #pragma unroll
        for (int s = 0; s < CHUNK; ++s) {
            const int t = c * CHUNK + s;
            const ULL* hr = &hb[t & 1][half][0];
            const ULL* xr = &xb[c & 1][half][s * FF];

            // 4 independent accumulator chains (2 output rows x 2 chains)
            ULL a0 = biasA, a1 = 0ULL;
            ULL c0 = biasB, c1 = 0ULL;

            // input projection (weights pre-scaled by C)
            #pragma unroll
            for (int f = 0; f < FF; f += 2) {
                ulonglong2 xv = *(const ulonglong2*)&xr[f];
                a0 = ffma2(xv.x, wihA[f],     a0);
                a1 = ffma2(xv.y, wihA[f + 1], a1);
                c0 = ffma2(xv.x, wihB[f],     c0);
                c1 = ffma2(xv.y, wihB[f + 1], c1);
            }
            // recurrent matvec: rows llo and llo+16
            #pragma unroll
            for (int j = 0; j < HH; j += 2) {
                ulonglong2 hv = *(const ulonglong2*)&hr[j];
                a0 = ffma2(hv.x, wA[j],     a0);
                a1 = ffma2(hv.y, wA[j + 1], a1);
                c0 = ffma2(hv.x, wB[j],     c0);
                c1 = ffma2(hv.y, wB[j + 1], c1);
            }
            const ULL accA = fadd2(a0, a1);
            const ULL accB = fadd2(c0, c1);

            float u0, u1, u2, u3;
            unpack2(accA, u0, u1);
            unpack2(accB, u2, u3);
            const float r0 = tanh_from_scaled(u0);
            const float r1 = tanh_from_scaled(u1);
            const float r2 = tanh_from_scaled(u2);
            const float r3 = tanh_from_scaled(u3);

            ULL* hw = &hb[(t + 1) & 1][half][0];
            hw[llo]      = pack2(r0, r1);
            hw[llo + 16] = pack2(r2, r3);
            __syncwarp();
        }
    }

    // ---- output head: y = h_final @ W_out^T + b_out ----
    // T=2048 even -> final h is in buffer 0. Lanes llo<8 of each half write
    // the 8 outputs for their pair's two batch rows.
    if (llo < OO) {
        const ULL* hf = &hb[0][half][0];
        float ya = b_out[llo];
        float yb = ya;
        #pragma unroll
        for (int j = 0; j < HH; ++j) {
            float ha, hc;
            unpack2(hf[j], ha, hc);
            const float wv = W_out[llo * HH + j];
            ya = fmaf(wv, ha, ya);
            yb = fmaf(wv, hc, yb);
        }
        const size_t r0 = base + 2 * half;
        out[r0 * OO + llo]       = ya;
        out[(r0 + 1) * OO + llo] = yb;
    }
}

extern "C" void kernel_launch(void* const* d_in, const int* in_sizes, int n_in,
                              void* d_out, int out_size)
{
    const float* x     = (const float*)d_in[0];
    const float* W_ih  = (const float*)d_in[1];
    const float* W_hh  = (const float*)d_in[2];
    const float* b_ih  = (const float*)d_in[3];
    const float* b_hh  = (const float*)d_in[4];
    const float* W_out = (const float*)d_in[5];
    const float* b_out = (const float*)d_in[6];
    float* out = (float*)d_out;

    // 4096 rows / 4 per warp = 1024 one-warp blocks (~7 per SM, one wave)
    rnn_fused_kernel<<<1024, 32>>>(x, W_ih, W_hh, b_ih, b_hh, W_out, b_out, out);
}